// round 16
// baseline (speedup 1.0000x reference)
#include <cuda_runtime.h>
#include <cuda_bf16.h>
#include <cuda_fp8.h>
#include <cstdint>

#define MDIM 8192
#define KDIM 4096
#define NDIM 4096

// ---------------- scratch (device globals; no allocation) ----------------
__device__ __nv_bfloat16 g_Xc[(size_t)MDIM * (KDIM / 2)];  // compressed 2:4 X values (bf16)
__device__ uint8_t g_Xm[(size_t)MDIM * (KDIM / 8)];        // 2:4 metadata: 4 bits / 4-group
__device__ __nv_bfloat16 g_Wq[(size_t)NDIM * KDIM];        // W fp8-grid values (bf16)
__device__ float g_xsc[MDIM];
__device__ float g_wsc[NDIM];

// ---------------- fp8 helpers ----------------
__device__ __forceinline__ uint8_t fp8_byte(float q) {
    return (uint8_t)__nv_cvt_float_to_fp8(q, __NV_SATFINITE, __NV_E4M3);
}
__device__ __forceinline__ float fp8_to_f32(uint8_t b) {
    __half_raw hr = __nv_cvt_fp8_to_halfraw((__nv_fp8_storage_t)b, __NV_E4M3);
    return __half2float(*reinterpret_cast<__half*>(&hr));
}

// ---------------- row loader + absmax ----------------
__device__ __forceinline__ float row_absmax_load(const float* __restrict__ src, int t, float* v) {
#pragma unroll
    for (int i = 0; i < 4; i++) {
        float4 f = reinterpret_cast<const float4*>(src)[t * 4 + i];
        v[i * 4 + 0] = f.x; v[i * 4 + 1] = f.y; v[i * 4 + 2] = f.z; v[i * 4 + 3] = f.w;
    }
    float am = 0.0f;
#pragma unroll
    for (int i = 0; i < 16; i++) am = fmaxf(am, fabsf(v[i]));
#pragma unroll
    for (int o = 16; o > 0; o >>= 1) am = fmaxf(am, __shfl_xor_sync(0xffffffffu, am, o));
    __shared__ float warpmax[8];
    if ((t & 31) == 0) warpmax[t >> 5] = am;
    __syncthreads();
    float amax = warpmax[0];
#pragma unroll
    for (int w = 1; w < 8; w++) amax = fmaxf(amax, warpmax[w]);
    return amax;
}

// ---------------- merged quant kernel (verified R15) ----------------
__global__ void __launch_bounds__(256) quant_all(const float* __restrict__ x,
                                                 const float* __restrict__ w) {
    const int t = threadIdx.x;

    if (blockIdx.x < MDIM) {
        const int row = blockIdx.x;
        float v[16];
        const float amax = row_absmax_load(x + (size_t)row * KDIM, t, v);
        const float scale = fmaxf(amax, 1e-12f) / 448.0f;
        const float rinv = 1.0f / scale;
        if (t == 0) g_xsc[row] = scale;

        __align__(16) __nv_bfloat16 cv[8];
        uint32_t meta = 0;
#pragma unroll
        for (int g = 0; g < 4; g++) {
            uint8_t qb[4];
            int key[4];
#pragma unroll
            for (int j = 0; j < 4; j++) {
                qb[j] = fp8_byte(v[g * 4 + j] * rinv);
                key[j] = ((int)(qb[j] & 0x7F) << 2) | (3 - j);
            }
            int ma = max(key[0], key[1]), na = min(key[0], key[1]);
            int mb = max(key[2], key[3]), nb = min(key[2], key[3]);
            int first = max(ma, mb);
            int sib = (ma >= mb) ? na : nb;
            int second = max(min(ma, mb), sib);
            int ia = 3 - (first & 3), ib = 3 - (second & 3);
            int i0 = min(ia, ib), i1 = max(ia, ib);
            meta |= (uint32_t)(i0 | (i1 << 2)) << (4 * g);
            uint8_t b0 = (i0 == 0) ? qb[0] : (i0 == 1) ? qb[1] : (i0 == 2) ? qb[2] : qb[3];
            uint8_t b1 = (i1 == 1) ? qb[1] : (i1 == 2) ? qb[2] : qb[3];
            cv[2 * g + 0] = __float2bfloat16(fp8_to_f32(b0));
            cv[2 * g + 1] = __float2bfloat16(fp8_to_f32(b1));
        }
        reinterpret_cast<uint4*>(g_Xc)[(size_t)row * 256 + t] = *reinterpret_cast<const uint4*>(cv);
        reinterpret_cast<uint16_t*>(g_Xm)[(size_t)row * 256 + t] = (uint16_t)meta;
    } else {
        const int row = blockIdx.x - MDIM;
        float v[16];
        const float amax = row_absmax_load(w + (size_t)row * KDIM, t, v);
        const float scale = fmaxf(amax, 1e-12f) / 448.0f;
        const float rinv = 1.0f / scale;
        if (t == 0) g_wsc[row] = scale;

        __align__(16) __nv_bfloat16 o[16];
#pragma unroll
        for (int i = 0; i < 16; i++)
            o[i] = __float2bfloat16(fp8_to_f32(fp8_byte(v[i] * rinv)));
        uint4* dst = reinterpret_cast<uint4*>(g_Wq + (size_t)row * KDIM) + t * 2;
        dst[0] = *reinterpret_cast<const uint4*>(&o[0]);
        dst[1] = *reinterpret_cast<const uint4*>(&o[8]);
    }
}

// ------- sparse GEMM: CTA 128x64, warp 32x32, 3 CTAs/SM (R11 per-warp code) -------
#define BM 128
#define BN 64
#define BK 128
#define NTHR 256
constexpr int A_TILE = 128 * 128;      // 16 KB compressed A (BM rows x 128B)
constexpr int BH_TILE = 64 * 128;      // 8 KB per B k-half (BN rows x 128B)
constexpr int B_TILE = 2 * BH_TILE;    // 16 KB
constexpr int M_TILE = 128 * 16;       // 2 KB metadata
constexpr int STAGE = A_TILE + B_TILE + M_TILE;   // 34816
constexpr unsigned DYN_SMEM = 2 * STAGE + 1024;   // 70656 -> 3 CTAs/SM (212 KB)

__device__ __forceinline__ void cp_async16(uint32_t smem_addr, const void* gmem_ptr) {
    asm volatile("cp.async.cg.shared.global [%0], [%1], 16;\n" :: "r"(smem_addr), "l"(gmem_ptr));
}
__device__ __forceinline__ uint32_t lds_u16(uint32_t a) {
    uint32_t v;
    asm volatile("ld.shared.u16 %0, [%1];" : "=r"(v) : "r"(a));
    return v;
}

__global__ void __launch_bounds__(NTHR, 3) gemm_sp(float* __restrict__ out) {
    extern __shared__ __align__(128) uint8_t dsm[];
    uint32_t raw = (uint32_t)__cvta_generic_to_shared(dsm);
    const uint32_t sbase = (raw + 1023u) & ~1023u;

    const int bm = blockIdx.y * BM;
    const int bn = blockIdx.x * BN;
    const int tid = threadIdx.x;
    const int lane = tid & 31;
    const int gid = lane >> 2;
    const int tig = lane & 3;
    const int warp = tid >> 5;          // 0..7
    const int wm = (warp >> 1) * 32;    // 4 warps along M (32 rows each)
    const int wn = (warp & 1) * 32;     // 2 warps along N (32 cols each)

    const __nv_bfloat16* gA = g_Xc + (size_t)bm * (KDIM / 2);
    const __nv_bfloat16* gB = g_Wq + (size_t)bn * KDIM;
    const uint8_t* gM = g_Xm + (size_t)bm * (KDIM / 8);

    auto load_tile = [&](int kt, int s) {
        const uint32_t sA = sbase + s * STAGE;
        const uint32_t sB = sA + A_TILE;
        const uint32_t sM = sA + A_TILE + B_TILE;
#pragma unroll
        for (int p = 0; p < 4; p++) {                  // A: 1024 16B chunks (128 rows x 8)
            int i = p * NTHR + tid;
            int r = i >> 3, kc = i & 7;
            cp_async16(sA + r * 128 + ((kc ^ (r & 7)) << 4),
                       gA + (size_t)r * (KDIM / 2) + kt * 64 + kc * 8);
        }
#pragma unroll
        for (int p = 0; p < 4; p++) {                  // B: 1024 chunks (64 rows x 16), 2 k-halves
            int i = p * NTHR + tid;
            int r = i >> 4, kc = i & 15;
            int kh = kc >> 3, k7 = kc & 7;
            cp_async16(sB + kh * BH_TILE + r * 128 + ((k7 ^ (r & 7)) << 4),
                       gB + (size_t)r * KDIM + kt * 128 + kc * 8);
        }
        if (tid < 128)                                 // metadata: 16B per row
            cp_async16(sM + tid * 16, gM + (size_t)tid * (KDIM / 8) + kt * 16);
    };

    float acc[2][4][4];
#pragma unroll
    for (int i = 0; i < 2; i++)
#pragma unroll
        for (int j = 0; j < 4; j++)
#pragma unroll
            for (int c = 0; c < 4; c++) acc[i][j][c] = 0.0f;

    const int T = KDIM / BK;  // 32
    load_tile(0, 0); asm volatile("cp.async.commit_group;\n" ::: "memory");
    load_tile(1, 1); asm volatile("cp.async.commit_group;\n" ::: "memory");

    const int half = lane & 1;

    for (int t = 0; t < T; t++) {
        asm volatile("cp.async.wait_group 1;\n" ::: "memory");
        __syncthreads();

        const uint32_t cA = sbase + (t & 1) * STAGE;
        const uint32_t cB = cA + A_TILE;
        const uint32_t cM = cA + A_TILE + B_TILE;

#pragma unroll
        for (int ks = 0; ks < 4; ks++) {
            uint32_t a[2][4];
#pragma unroll
            for (int mi = 0; mi < 2; mi++) {
                int row = wm + mi * 16 + (lane & 15);
                int kc = ks * 2 + (lane >> 4);
                uint32_t sa = cA + row * 128 + ((kc ^ (row & 7)) << 4);
                asm volatile("ldmatrix.sync.aligned.m8n8.x4.shared.b16 {%0,%1,%2,%3}, [%4];\n"
                             : "=r"(a[mi][0]), "=r"(a[mi][1]), "=r"(a[mi][2]), "=r"(a[mi][3])
                             : "r"(sa));
            }
            uint32_t e[2];
#pragma unroll
            for (int mi = 0; mi < 2; mi++) {
                int r0 = wm + mi * 16 + gid;
                uint32_t lo = lds_u16(cM + r0 * 16 + ks * 4 + half * 2);
                uint32_t hi = lds_u16(cM + (r0 + 8) * 16 + ks * 4 + half * 2);
                e[mi] = lo | (hi << 16);
            }
            uint32_t b[4][4];
            const int kh = ks >> 1;
            const int cb = (ks & 1) * 4;
#pragma unroll
            for (int j = 0; j < 2; j++) {
                int rowb = wn + j * 16 + (lane & 15);
                uint32_t base = cB + kh * BH_TILE + rowb * 128;
                uint32_t r0, r1, r2, r3;
                uint32_t ad1 = base + (((cb + (lane >> 4)) ^ (rowb & 7)) << 4);
                asm volatile("ldmatrix.sync.aligned.m8n8.x4.shared.b16 {%0,%1,%2,%3}, [%4];\n"
                             : "=r"(r0), "=r"(r1), "=r"(r2), "=r"(r3) : "r"(ad1));
                b[2 * j][0] = r0; b[2 * j + 1][0] = r1;
                b[2 * j][1] = r2; b[2 * j + 1][1] = r3;
                uint32_t ad2 = base + (((cb + 2 + (lane >> 4)) ^ (rowb & 7)) << 4);
                asm volatile("ldmatrix.sync.aligned.m8n8.x4.shared.b16 {%0,%1,%2,%3}, [%4];\n"
                             : "=r"(r0), "=r"(r1), "=r"(r2), "=r"(r3) : "r"(ad2));
                b[2 * j][2] = r0; b[2 * j + 1][2] = r1;
                b[2 * j][3] = r2; b[2 * j + 1][3] = r3;
            }
#pragma unroll
            for (int mi = 0; mi < 2; mi++)
#pragma unroll
                for (int nj = 0; nj < 4; nj++) {
                    asm volatile(
                        "mma.sp::ordered_metadata.sync.aligned.m16n8k32.row.col.f32.bf16.bf16.f32 "
                        "{%0,%1,%2,%3}, {%4,%5,%6,%7}, {%8,%9,%10,%11}, {%0,%1,%2,%3}, %12, 0x0;\n"
                        : "+f"(acc[mi][nj][0]), "+f"(acc[mi][nj][1]),
                          "+f"(acc[mi][nj][2]), "+f"(acc[mi][nj][3])
                        : "r"(a[mi][0]), "r"(a[mi][1]), "r"(a[mi][2]), "r"(a[mi][3]),
                          "r"(b[nj][0]), "r"(b[nj][1]), "r"(b[nj][2]), "r"(b[nj][3]),
                          "r"(e[mi]));
                }
        }
        __syncthreads();
        if (t + 2 < T) {
            load_tile(t + 2, t & 1);
            asm volatile("cp.async.commit_group;\n" ::: "memory");
        }
    }

    // epilogue: f32 stores of bf16-rounded scaled accumulators (verified mapping)
#pragma unroll
    for (int mi = 0; mi < 2; mi++) {
#pragma unroll
        for (int h = 0; h < 2; h++) {
            int m = bm + wm + mi * 16 + h * 8 + gid;
            float xs = g_xsc[m];
#pragma unroll
            for (int nj = 0; nj < 4; nj++) {
                int n = bn + wn + nj * 8 + tig * 2;
                float c0 = acc[mi][nj][h * 2 + 0] * xs * g_wsc[n];
                float c1 = acc[mi][nj][h * 2 + 1] * xs * g_wsc[n + 1];
                float2 pv;
                pv.x = __bfloat162float(__float2bfloat16(c0));
                pv.y = __bfloat162float(__float2bfloat16(c1));
                *reinterpret_cast<float2*>(out + (size_t)m * NDIM + n) = pv;
            }
        }
    }
}

extern "C" void kernel_launch(void* const* d_in, const int* in_sizes, int n_in,
                              void* d_out, int out_size) {
    const float* in0 = (const float*)d_in[0];
    const float* in1 = (const float*)d_in[1];
    const float* x = in0;
    const float* w = in1;
    if (n_in >= 2 && in_sizes[0] == NDIM * KDIM && in_sizes[1] == MDIM * KDIM) {
        x = in1; w = in0;
    }
    float* out = (float*)d_out;
    (void)out_size;

    cudaFuncSetAttribute(gemm_sp, cudaFuncAttributeMaxDynamicSharedMemorySize, DYN_SMEM);

    quant_all<<<MDIM + NDIM, 256>>>(x, w);

    dim3 grid(NDIM / BN, MDIM / BM);   // (64, 64)
    gemm_sp<<<grid, NTHR, DYN_SMEM>>>(out);
}

// round 17
// speedup vs baseline: 1.0538x; 1.0538x over previous
#include <cuda_runtime.h>
#include <cuda_bf16.h>
#include <cuda_fp8.h>
#include <cstdint>

#define MDIM 8192
#define KDIM 4096
#define NDIM 4096

// ---------------- scratch (device globals; no allocation) ----------------
__device__ __nv_bfloat16 g_Xc[(size_t)MDIM * (KDIM / 2)];  // compressed 2:4 X values (bf16)
__device__ uint8_t g_Xm[(size_t)MDIM * (KDIM / 8)];        // 2:4 metadata: 4 bits / 4-group
__device__ __nv_bfloat16 g_Wq[(size_t)NDIM * KDIM];        // W fp8-grid values (bf16)
__device__ float g_xsc[MDIM];
__device__ float g_wsc[NDIM];

// ---------------- paired fp8 helpers ----------------
__device__ __forceinline__ uint32_t fp8x2_from(float a, float b) {
    // returns (cvt(b) << 8) | cvt(a)  -- x -> low byte per cuda_fp8 impl
    return (uint32_t)__nv_cvt_float2_to_fp8x2(make_float2(a, b), __NV_SATFINITE, __NV_E4M3);
}
__device__ __forceinline__ __nv_bfloat162 fp8x2_to_bf162(uint32_t pk) {
    __half2_raw h2 = __nv_cvt_fp8x2_to_halfraw2((__nv_fp8x2_storage_t)pk, __NV_E4M3);
    float2 fv = __half22float2(*reinterpret_cast<__half2*>(&h2));
    return __float22bfloat162_rn(fv);
}

// ---------------- row loader + absmax ----------------
__device__ __forceinline__ float row_absmax_load(const float* __restrict__ src, int t, float* v) {
#pragma unroll
    for (int i = 0; i < 4; i++) {
        float4 f = reinterpret_cast<const float4*>(src)[t * 4 + i];
        v[i * 4 + 0] = f.x; v[i * 4 + 1] = f.y; v[i * 4 + 2] = f.z; v[i * 4 + 3] = f.w;
    }
    float am = 0.0f;
#pragma unroll
    for (int i = 0; i < 16; i++) am = fmaxf(am, fabsf(v[i]));
#pragma unroll
    for (int o = 16; o > 0; o >>= 1) am = fmaxf(am, __shfl_xor_sync(0xffffffffu, am, o));
    __shared__ float warpmax[8];
    if ((t & 31) == 0) warpmax[t >> 5] = am;
    __syncthreads();
    float amax = warpmax[0];
#pragma unroll
    for (int w = 1; w < 8; w++) amax = fmaxf(amax, warpmax[w]);
    return amax;
}

// ---------------- merged quant kernel (paired converts) ----------------
__global__ void __launch_bounds__(256) quant_all(const float* __restrict__ x,
                                                 const float* __restrict__ w) {
    const int t = threadIdx.x;

    if (blockIdx.x < MDIM) {
        const int row = blockIdx.x;
        float v[16];
        const float amax = row_absmax_load(x + (size_t)row * KDIM, t, v);
        const float scale = fmaxf(amax, 1e-12f) / 448.0f;
        const float rinv = 1.0f / scale;
        if (t == 0) g_xsc[row] = scale;

        __align__(16) __nv_bfloat162 cv[4];
        uint32_t meta = 0;
#pragma unroll
        for (int g = 0; g < 4; g++) {
            uint32_t p01 = fp8x2_from(v[g * 4 + 0] * rinv, v[g * 4 + 1] * rinv);
            uint32_t p23 = fp8x2_from(v[g * 4 + 2] * rinv, v[g * 4 + 3] * rinv);
            uint8_t qb[4] = { (uint8_t)(p01 & 0xFF), (uint8_t)(p01 >> 8),
                              (uint8_t)(p23 & 0xFF), (uint8_t)(p23 >> 8) };
            int key[4];
#pragma unroll
            for (int j = 0; j < 4; j++)
                key[j] = ((int)(qb[j] & 0x7F) << 2) | (3 - j);
            int ma = max(key[0], key[1]), na = min(key[0], key[1]);
            int mb = max(key[2], key[3]), nb = min(key[2], key[3]);
            int first = max(ma, mb);
            int sib = (ma >= mb) ? na : nb;
            int second = max(min(ma, mb), sib);
            int ia = 3 - (first & 3), ib = 3 - (second & 3);
            int i0 = min(ia, ib), i1 = max(ia, ib);
            meta |= (uint32_t)(i0 | (i1 << 2)) << (4 * g);
            uint8_t b0 = (i0 == 0) ? qb[0] : (i0 == 1) ? qb[1] : (i0 == 2) ? qb[2] : qb[3];
            uint8_t b1 = (i1 == 1) ? qb[1] : (i1 == 2) ? qb[2] : qb[3];
            cv[g] = fp8x2_to_bf162((uint32_t)b0 | ((uint32_t)b1 << 8));
        }
        reinterpret_cast<uint4*>(g_Xc)[(size_t)row * 256 + t] = *reinterpret_cast<const uint4*>(cv);
        reinterpret_cast<uint16_t*>(g_Xm)[(size_t)row * 256 + t] = (uint16_t)meta;
    } else {
        const int row = blockIdx.x - MDIM;
        float v[16];
        const float amax = row_absmax_load(w + (size_t)row * KDIM, t, v);
        const float scale = fmaxf(amax, 1e-12f) / 448.0f;
        const float rinv = 1.0f / scale;
        if (t == 0) g_wsc[row] = scale;

        __align__(16) __nv_bfloat162 o[8];
#pragma unroll
        for (int i = 0; i < 8; i++) {
            uint32_t p = fp8x2_from(v[2 * i] * rinv, v[2 * i + 1] * rinv);
            o[i] = fp8x2_to_bf162(p);
        }
        uint4* dst = reinterpret_cast<uint4*>(g_Wq + (size_t)row * KDIM) + t * 2;
        dst[0] = *reinterpret_cast<const uint4*>(&o[0]);
        dst[1] = *reinterpret_cast<const uint4*>(&o[4]);
    }
}

// ---------------- sparse GEMM: R11 VERBATIM (measured 560 us; LOCKED) ----------------
#define BM 128
#define BN 128
#define BK 128
#define NTHR 256
constexpr int A_TILE = 128 * 128;    // 16 KB compressed A
constexpr int B_TILE = 128 * 256;    // 32 KB B (two k-half tiles)
constexpr int M_TILE = 128 * 16;     // 2 KB metadata
constexpr int STAGE = A_TILE + B_TILE + M_TILE;   // 51200
constexpr unsigned DYN_SMEM = 2 * STAGE + 1024;   // 103424 -> 2 CTAs/SM

__device__ __forceinline__ void cp_async16(uint32_t smem_addr, const void* gmem_ptr) {
    asm volatile("cp.async.cg.shared.global [%0], [%1], 16;\n" :: "r"(smem_addr), "l"(gmem_ptr));
}
__device__ __forceinline__ uint32_t lds_u16(uint32_t a) {
    uint32_t v;
    asm volatile("ld.shared.u16 %0, [%1];" : "=r"(v) : "r"(a));
    return v;
}

__global__ void __launch_bounds__(NTHR, 2) gemm_sp(float* __restrict__ out) {
    extern __shared__ __align__(128) uint8_t dsm[];
    uint32_t raw = (uint32_t)__cvta_generic_to_shared(dsm);
    const uint32_t sbase = (raw + 1023u) & ~1023u;

    const int bm = blockIdx.y * BM;
    const int bn = blockIdx.x * BN;
    const int tid = threadIdx.x;
    const int lane = tid & 31;
    const int gid = lane >> 2;
    const int tig = lane & 3;
    const int warp = tid >> 5;          // 0..7
    const int wm = (warp >> 2) * 64;    // 2 warps along M (64 rows)
    const int wn = (warp & 3) * 32;     // 4 warps along N (32 cols)

    const __nv_bfloat16* gA = g_Xc + (size_t)bm * (KDIM / 2);
    const __nv_bfloat16* gB = g_Wq + (size_t)bn * KDIM;
    const uint8_t* gM = g_Xm + (size_t)bm * (KDIM / 8);

    auto load_tile = [&](int kt, int s) {
        const uint32_t sA = sbase + s * STAGE;
        const uint32_t sB = sA + A_TILE;
        const uint32_t sM = sA + A_TILE + B_TILE;
#pragma unroll
        for (int p = 0; p < 4; p++) {                  // A: 1024 16B chunks
            int i = p * NTHR + tid;
            int r = i >> 3, kc = i & 7;
            cp_async16(sA + r * 128 + ((kc ^ (r & 7)) << 4),
                       gA + (size_t)r * (KDIM / 2) + kt * 64 + kc * 8);
        }
#pragma unroll
        for (int p = 0; p < 8; p++) {                  // B: 2048 chunks, two k-halves
            int i = p * NTHR + tid;
            int r = i >> 4, kc = i & 15;
            int kh = kc >> 3, k7 = kc & 7;
            cp_async16(sB + kh * 16384 + r * 128 + ((k7 ^ (r & 7)) << 4),
                       gB + (size_t)r * KDIM + kt * 128 + kc * 8);
        }
        if (tid < 128)                                 // metadata: 16B per row
            cp_async16(sM + tid * 16, gM + (size_t)tid * (KDIM / 8) + kt * 16);
    };

    float acc[4][4][4];
#pragma unroll
    for (int i = 0; i < 4; i++)
#pragma unroll
        for (int j = 0; j < 4; j++)
#pragma unroll
            for (int c = 0; c < 4; c++) acc[i][j][c] = 0.0f;

    const int T = KDIM / BK;  // 32
    load_tile(0, 0); asm volatile("cp.async.commit_group;\n" ::: "memory");
    load_tile(1, 1); asm volatile("cp.async.commit_group;\n" ::: "memory");

    const int half = lane & 1;

    for (int t = 0; t < T; t++) {
        asm volatile("cp.async.wait_group 1;\n" ::: "memory");
        __syncthreads();

        const uint32_t cA = sbase + (t & 1) * STAGE;
        const uint32_t cB = cA + A_TILE;
        const uint32_t cM = cA + A_TILE + B_TILE;

#pragma unroll
        for (int ks = 0; ks < 4; ks++) {
            uint32_t a[4][4];
#pragma unroll
            for (int mi = 0; mi < 4; mi++) {
                int row = wm + mi * 16 + (lane & 15);
                int kc = ks * 2 + (lane >> 4);
                uint32_t sa = cA + row * 128 + ((kc ^ (row & 7)) << 4);
                asm volatile("ldmatrix.sync.aligned.m8n8.x4.shared.b16 {%0,%1,%2,%3}, [%4];\n"
                             : "=r"(a[mi][0]), "=r"(a[mi][1]), "=r"(a[mi][2]), "=r"(a[mi][3])
                             : "r"(sa));
            }
            uint32_t e[4];
#pragma unroll
            for (int mi = 0; mi < 4; mi++) {
                int r0 = wm + mi * 16 + gid;
                uint32_t lo = lds_u16(cM + r0 * 16 + ks * 4 + half * 2);
                uint32_t hi = lds_u16(cM + (r0 + 8) * 16 + ks * 4 + half * 2);
                e[mi] = lo | (hi << 16);
            }
            uint32_t b[4][4];
            const int kh = ks >> 1;
            const int cb = (ks & 1) * 4;
#pragma unroll
            for (int j = 0; j < 2; j++) {
                int rowb = wn + j * 16 + (lane & 15);
                uint32_t base = cB + kh * 16384 + rowb * 128;
                uint32_t r0, r1, r2, r3;
                uint32_t ad1 = base + (((cb + (lane >> 4)) ^ (rowb & 7)) << 4);
                asm volatile("ldmatrix.sync.aligned.m8n8.x4.shared.b16 {%0,%1,%2,%3}, [%4];\n"
                             : "=r"(r0), "=r"(r1), "=r"(r2), "=r"(r3) : "r"(ad1));
                b[2 * j][0] = r0; b[2 * j + 1][0] = r1;
                b[2 * j][1] = r2; b[2 * j + 1][1] = r3;
                uint32_t ad2 = base + (((cb + 2 + (lane >> 4)) ^ (rowb & 7)) << 4);
                asm volatile("ldmatrix.sync.aligned.m8n8.x4.shared.b16 {%0,%1,%2,%3}, [%4];\n"
                             : "=r"(r0), "=r"(r1), "=r"(r2), "=r"(r3) : "r"(ad2));
                b[2 * j][2] = r0; b[2 * j + 1][2] = r1;
                b[2 * j][3] = r2; b[2 * j + 1][3] = r3;
            }
#pragma unroll
            for (int mi = 0; mi < 4; mi++)
#pragma unroll
                for (int nj = 0; nj < 4; nj++) {
                    asm volatile(
                        "mma.sp::ordered_metadata.sync.aligned.m16n8k32.row.col.f32.bf16.bf16.f32 "
                        "{%0,%1,%2,%3}, {%4,%5,%6,%7}, {%8,%9,%10,%11}, {%0,%1,%2,%3}, %12, 0x0;\n"
                        : "+f"(acc[mi][nj][0]), "+f"(acc[mi][nj][1]),
                          "+f"(acc[mi][nj][2]), "+f"(acc[mi][nj][3])
                        : "r"(a[mi][0]), "r"(a[mi][1]), "r"(a[mi][2]), "r"(a[mi][3]),
                          "r"(b[nj][0]), "r"(b[nj][1]), "r"(b[nj][2]), "r"(b[nj][3]),
                          "r"(e[mi]));
                }
        }
        __syncthreads();
        if (t + 2 < T) {
            load_tile(t + 2, t & 1);
            asm volatile("cp.async.commit_group;\n" ::: "memory");
        }
    }

    // epilogue: f32 stores of bf16-rounded scaled accumulators (verified mapping)
#pragma unroll
    for (int mi = 0; mi < 4; mi++) {
#pragma unroll
        for (int h = 0; h < 2; h++) {
            int m = bm + wm + mi * 16 + h * 8 + gid;
            float xs = g_xsc[m];
#pragma unroll
            for (int nj = 0; nj < 4; nj++) {
                int n = bn + wn + nj * 8 + tig * 2;
                float c0 = acc[mi][nj][h * 2 + 0] * xs * g_wsc[n];
                float c1 = acc[mi][nj][h * 2 + 1] * xs * g_wsc[n + 1];
                float2 pv;
                pv.x = __bfloat162float(__float2bfloat16(c0));
                pv.y = __bfloat162float(__float2bfloat16(c1));
                *reinterpret_cast<float2*>(out + (size_t)m * NDIM + n) = pv;
            }
        }
    }
}

extern "C" void kernel_launch(void* const* d_in, const int* in_sizes, int n_in,
                              void* d_out, int out_size) {
    const float* in0 = (const float*)d_in[0];
    const float* in1 = (const float*)d_in[1];
    const float* x = in0;
    const float* w = in1;
    if (n_in >= 2 && in_sizes[0] == NDIM * KDIM && in_sizes[1] == MDIM * KDIM) {
        x = in1; w = in0;
    }
    float* out = (float*)d_out;
    (void)out_size;

    cudaFuncSetAttribute(gemm_sp, cudaFuncAttributeMaxDynamicSharedMemorySize, DYN_SMEM);

    quant_all<<<MDIM + NDIM, 256>>>(x, w);

    dim3 grid(NDIM / BN, MDIM / BM);   // (32, 64)
    gemm_sp<<<grid, NTHR, DYN_SMEM>>>(out);
}